// round 15
// baseline (speedup 1.0000x reference)
#include <cuda_runtime.h>
#include <cuda_fp16.h>
#include <cstdint>

// ---------------- problem constants ----------------
#define CC   54
#define CP   27
#define MM   6
#define TT   20
#define NCAND 120
#define CTPAD 56
#define C1F  1.191042e-8f
#define C2F  1.4387752f

// ---------------- mma tile config ----------------
#define TILE_M 128                 // pixels per block tile (8 warps x 16)
#define NNT    15                  // n-tiles of 8 (120 candidates)
#define AROW   128                 // bytes per A row (64 fp16)
#define BROW   128                 // bytes per B row (64 fp16)
#define A32ROW 216                 // bytes per fp32 s_obs row (27 float2)
#define A32BUF (TILE_M * A32ROW)   // 27648 per buffer
#define B_IMG_BYTES (NCAND * BROW) // 15360

// smem layout (byte offsets from 1024-aligned base)
#define SM_A    0                  // 128 x 128B swizzled fp16 A tile      (16384)
#define SM_B    16384              // 120 x 128B swizzled fp16 candidates  (15360)
#define SM_A32  31744              // 2 x (128 x 216B) fp32 s_obs rows     (55296)
#define SM_C2P  87040              // 120 f32: c2 + 1e-6   (pad 512)
#define SM_C2M  87552              // 120 f32: c2 - 1e-6   (pad 512)
#define SM_MINV 88064              // 128 f32
#define SM_MINK 88576              // 128 i32
#define SM_TC   89088              // 20 f32
#define SM_LM   89168              // 8 f32
#define SM_LIB  89200              // 6*54 f32
#define SM_END  90496
#define DYNSMEM (SM_END + 1024)

// ---------------- device globals ----------------
__device__ __align__(16) unsigned char g_Bimg[B_IMG_BYTES];
__device__ __align__(16) float g_candT[NCAND * CTPAD];
__device__ float  g_c2[NCAND];
__device__ float  g_tc[TT];
__device__ float  g_lm[MM];
__device__ double g_obj;

__device__ __forceinline__ uint32_t smem_u32(const void* p) {
    uint32_t a;
    asm("{ .reg .u64 t; cvta.to.shared.u64 t, %1; cvt.u32.u64 %0, t; }" : "=r"(a) : "l"(p));
    return a;
}
__device__ __forceinline__ void ldsm_x4(uint32_t& r0, uint32_t& r1, uint32_t& r2, uint32_t& r3, uint32_t addr) {
    asm volatile("ldmatrix.sync.aligned.m8n8.x4.shared.b16 {%0,%1,%2,%3}, [%4];"
        : "=r"(r0), "=r"(r1), "=r"(r2), "=r"(r3) : "r"(addr));
}
__device__ __forceinline__ void ldsm_x2(uint32_t& r0, uint32_t& r1, uint32_t addr) {
    asm volatile("ldmatrix.sync.aligned.m8n8.x2.shared.b16 {%0,%1}, [%2];"
        : "=r"(r0), "=r"(r1) : "r"(addr));
}
__device__ __forceinline__ void mma16816h(float* d, uint32_t a0, uint32_t a1, uint32_t a2, uint32_t a3,
                                          uint32_t b0, uint32_t b1) {
    asm volatile("mma.sync.aligned.m16n8k16.row.col.f32.f16.f16.f32 "
        "{%0,%1,%2,%3}, {%4,%5,%6,%7}, {%8,%9}, {%0,%1,%2,%3};"
        : "+f"(d[0]), "+f"(d[1]), "+f"(d[2]), "+f"(d[3])
        : "r"(a0), "r"(a1), "r"(a2), "r"(a3), "r"(b0), "r"(b1));
}
__device__ __forceinline__ void cp_async8(uint32_t dst, const void* src) {
    asm volatile("cp.async.ca.shared.global [%0], [%1], 8;" :: "r"(dst), "l"(src) : "memory");
}
__device__ __forceinline__ void cp_async_commit() {
    asm volatile("cp.async.commit_group;" ::: "memory");
}
__device__ __forceinline__ void cp_async_wait0() {
    asm volatile("cp.async.wait_group 0;" ::: "memory");
}

// ---------------------------------------------------------------------------
// Setup: fp16 swizzled candidate B image + exact fp32 tables.
// ---------------------------------------------------------------------------
__global__ void hadar_setup(const float* __restrict__ s_sky,
                            const float* __restrict__ s_ground,
                            const float* __restrict__ library,
                            const float* __restrict__ wg) {
    __shared__ float sh_xamb[CC];
    __shared__ float sh_B[TT][CC];
    __shared__ float sh_lib[MM][CC];
    int tid = threadIdx.x;
    if (tid == 0) g_obj = 0.0;
    for (int c = tid; c < CC; c += blockDim.x)
        sh_xamb[c] = 0.5f * s_sky[c] + 0.5f * s_ground[c];
    for (int i = tid; i < MM * CC; i += blockDim.x)
        sh_lib[i / CC][i % CC] = library[i];
    for (int i = tid; i < TT * CC; i += blockDim.x) {
        int t = i / CC, c = i % CC;
        float Tk = 250.0f + (100.0f / 19.0f) * (float)t;
        float nu = wg[c];
        sh_B[t][c] = C1F * nu * nu * nu / expm1f(C2F * nu / Tk);
    }
    if (tid < TT) g_tc[tid] = 250.0f + (100.0f / 19.0f) * (float)tid;
    __syncthreads();
    if (tid < MM) {
        float s = 0.0f;
        for (int c = 0; c < CC; c++) s += sh_lib[tid][c];
        g_lm[tid] = s / (float)CC;
    }
    for (int i = tid; i < NCAND * CC; i += blockDim.x) {
        int k = i / CC, c = i % CC;
        int m = k / TT, t = k % TT;
        float e = sh_lib[m][c];
        g_candT[k * CTPAD + c] = e * sh_B[t][c] + (1.0f - e) * sh_xamb[c];
    }
    for (int k = tid; k < NCAND; k += blockDim.x) {
        int m = k / TT, t = k % TT;
        float s = 0.0f;
        for (int c = 0; c < CC; c++) {
            float e = sh_lib[m][c];
            float v = e * sh_B[t][c] + (1.0f - e) * sh_xamb[c];
            s += v * v;
        }
        g_c2[k] = s;
    }
    // fp16 B image: row n (candidate), 64 cols (54 real + 10 zeros), XOR-swizzled.
    for (int i = tid; i < NCAND * 64; i += blockDim.x) {
        int n = i / 64, c = i % 64;
        float v = 0.0f;
        if (c < CC) {
            int m = n / TT, t = n % TT;
            float e = sh_lib[m][c];
            v = e * sh_B[t][c] + (1.0f - e) * sh_xamb[c];
        }
        __half h = __float2half(v);
        uint32_t raw = (uint32_t)(2 * c);
        uint32_t phys = (uint32_t)n * BROW + (raw ^ (((uint32_t)n & 7u) << 4));
        *(__half*)(g_Bimg + phys) = h;
    }
}

// ---------------------------------------------------------------------------
// Main: persistent coarse-fp16-HMMA + sound exact-fp32 refine.
// Double-buffered cp.async prefetch covered by the MMA section.
// 256 threads, 8 warps; each warp owns 16 pixels of each 128-px tile.
// ---------------------------------------------------------------------------
__global__ __launch_bounds__(256, 2)
void hadar_main_mma(const float* __restrict__ s_obs,
                    const float* __restrict__ library,
                    float* __restrict__ out, int N) {
    extern __shared__ unsigned char dynsmem[];
    uint32_t raw = smem_u32(dynsmem);
    uint32_t padb = (1024u - (raw & 1023u)) & 1023u;
    uint32_t sb = raw + padb;
    unsigned char* sp = dynsmem + padb;

    int tid = threadIdx.x, wid = tid >> 5, lane = tid & 31;

    // one-time smem fill
    {
        const uint4* srcB = (const uint4*)g_Bimg;
        uint4* dstB = (uint4*)(sp + SM_B);
        for (int i = tid; i < B_IMG_BYTES / 16; i += 256) dstB[i] = srcB[i];
        float* c2p = (float*)(sp + SM_C2P);
        float* c2m = (float*)(sp + SM_C2M);
        for (int i = tid; i < NCAND; i += 256) {
            float v = g_c2[i];
            c2p[i] = v + 1e-6f;
            c2m[i] = v - 1e-6f;
        }
        if (tid < TT) ((float*)(sp + SM_TC))[tid] = g_tc[tid];
        if (tid < MM) ((float*)(sp + SM_LM))[tid] = g_lm[tid];
        float* libd = (float*)(sp + SM_LIB);
        for (int i = tid; i < MM * CC; i += 256) libd[i] = library[i];
    }
    __syncthreads();

    long long NN = N;
    int tiles = (N + TILE_M - 1) / TILE_M;
    double acc = 0.0;            // Σ minv (own pixels) + Σ x^2+y^2 (own elements)

    const int r0 = wid << 4;     // warp's first row in the 128-row tile
    const uint32_t abase = sb + SM_A + (uint32_t)r0 * AROW;
    const int a_mi = lane >> 3;
    const uint32_t a_row = (uint32_t)(((a_mi & 1) << 3) + (lane & 7));
    const uint32_t a_sw = (a_row & 7u) << 4;
    const uint32_t a_hi16 = (uint32_t)((a_mi >> 1) << 4);
    const uint32_t a_rowoff = abase + a_row * AROW;
    const uint32_t b4_row = (uint32_t)(((lane >> 4) << 3) + (lane & 7));
    const uint32_t b4_sw = ((uint32_t)(lane & 7)) << 4;
    const uint32_t b4_hi16 = (uint32_t)(((lane >> 3) & 1) << 4);
    const uint32_t b4_base = sb + SM_B + b4_row * BROW;
    const int l15 = lane & 15;
    const uint32_t b2_sw = ((uint32_t)(l15 & 7)) << 4;
    const uint32_t b2_hi16 = (uint32_t)((l15 >> 3) << 4);
    const uint32_t b2_base = sb + SM_B + (uint32_t)(14 * 8 + (l15 & 7)) * BROW;

    const float* c2ps = (const float*)(sp + SM_C2P);
    const float* c2ms = (const float*)(sp + SM_C2M);
    const int ra = r0 + (lane >> 2);              // row a; row b = ra + 8
    const int colbase = 2 * (lane & 3);
    int* mkw = (int*)(sp + SM_MINK) + r0;         // warp-private slots
    float* mvw = (float*)(sp + SM_MINV) + r0;
    const uint32_t a32wbase = sb + SM_A32 + (uint32_t)r0 * A32ROW + (uint32_t)lane * 8u;

    // ---- prologue: cp.async first tile into buffer 0 ----
    {
        long long base0 = (long long)blockIdx.x * TILE_M + r0;
        if (blockIdx.x < tiles && lane < CP) {
#pragma unroll
            for (int rr = 0; rr < 16; rr++) {
                long long n = base0 + rr;
                if (n < N)
                    cp_async8(a32wbase + (uint32_t)rr * A32ROW, s_obs + n * CC + 2 * lane);
            }
        }
        cp_async_commit();
    }

    uint32_t pb = 0;   // current A32 buffer

    for (int tile = blockIdx.x; tile < tiles; tile += gridDim.x) {
        long long base = (long long)tile * TILE_M;
        long long wbase = base + r0;
        const uint32_t curof = pb * (uint32_t)A32BUF;

        cp_async_wait0();
        __syncwarp();

        // ---- stage A: read fp32 rows from cur buffer, convert, fp16 STS ----
        float tp2 = 0.0f;
#pragma unroll
        for (int rr = 0; rr < 16; rr++) {
            int r = r0 + rr;
            float x = 0.0f, y = 0.0f;
            if (lane < CP) {
                float2 v = *(const float2*)(sp + SM_A32 + curof + (uint32_t)r * A32ROW + (uint32_t)lane * 8u);
                x = v.x; y = v.y;
            }
            tp2 = fmaf(x, x, fmaf(y, y, tp2));
            __half2 h2 = __floats2half2_rn(x, y);
            uint32_t hp = *(uint32_t*)&h2;
            uint32_t sw = ((uint32_t)r & 7u) << 4;
            *(uint32_t*)(sp + SM_A + (uint32_t)r * AROW + ((4u * (uint32_t)lane) ^ sw)) = hp;
        }
        acc += (double)tp2;
        __syncwarp();

        // ---- cp.async NEXT tile into other buffer (covered by MMA below) ----
        {
            int ntile = tile + gridDim.x;
            if (ntile < tiles && lane < CP) {
                long long nbase = (long long)ntile * TILE_M + r0;
                uint32_t dst = a32wbase + (curof ^ (uint32_t)A32BUF);
#pragma unroll
                for (int rr = 0; rr < 16; rr++) {
                    long long n = nbase + rr;
                    if (n < N)
                        cp_async8(dst + (uint32_t)rr * A32ROW, s_obs + n * CC + 2 * lane);
                }
            }
            cp_async_commit();
        }

        // ---- coarse HMMA: D[16 x 120], K=64 fp16 (warp-local A rows) ----
        float d[NNT * 4];
#pragma unroll
        for (int i = 0; i < NNT * 4; i++) d[i] = 0.0f;

#pragma unroll
        for (int s = 0; s < 4; s++) {
            uint32_t koff = (uint32_t)s * 32u;
            uint32_t a0, a1, a2, a3;
            ldsm_x4(a0, a1, a2, a3, a_rowoff + ((koff + a_hi16) ^ a_sw));
            uint32_t bk4 = (koff + b4_hi16) ^ b4_sw;
#pragma unroll
            for (int q = 0; q < 7; q++) {
                uint32_t b0, b1, b2, b3;
                ldsm_x4(b0, b1, b2, b3, b4_base + (uint32_t)q * (16u * BROW) + bk4);
                mma16816h(d + (2 * q) * 4,     a0, a1, a2, a3, b0, b1);
                mma16816h(d + (2 * q + 1) * 4, a0, a1, a2, a3, b2, b3);
            }
            {
                uint32_t b0, b1;
                ldsm_x2(b0, b1, b2_base + ((koff + b2_hi16) ^ b2_sw));
                mma16816h(d + 14 * 4, a0, a1, a2, a3, b0, b1);
            }
        }

        // ---- pass 1: m1 = min(hi), hi = c2+1e-6 - 1.9978*dot (split chains) ----
        float m1a0 = 3.402823e38f, m1a1 = 3.402823e38f;
        float m1b0 = 3.402823e38f, m1b1 = 3.402823e38f;
#pragma unroll
        for (int nt = 0; nt < NNT; nt++) {
            int k0 = nt * 8 + colbase;
            float p0 = c2ps[k0], p1 = c2ps[k0 + 1];
            m1a0 = fminf(m1a0, fmaf(-1.9978f, d[nt * 4 + 0], p0));
            m1a1 = fminf(m1a1, fmaf(-1.9978f, d[nt * 4 + 1], p1));
            m1b0 = fminf(m1b0, fmaf(-1.9978f, d[nt * 4 + 2], p0));
            m1b1 = fminf(m1b1, fmaf(-1.9978f, d[nt * 4 + 3], p1));
        }
        float m1a = fminf(m1a0, m1a1);
        float m1b = fminf(m1b0, m1b1);
#pragma unroll
        for (int off = 1; off <= 2; off <<= 1) {
            m1a = fminf(m1a, __shfl_xor_sync(0xffffffffu, m1a, off));
            m1b = fminf(m1b, __shfl_xor_sync(0xffffffffu, m1b, off));
        }

        // ---- pass 2: shortlist masks (lo = c2-1e-6 - 2.0022*dot <= m1) ----
        uint32_t maskA = 0, maskB = 0;
#pragma unroll
        for (int nt = 0; nt < NNT; nt++) {
            int k0 = nt * 8 + colbase;
            float q0 = c2ms[k0], q1 = c2ms[k0 + 1];
            if (fmaf(-2.0022f, d[nt * 4 + 0], q0) <= m1a) maskA |= 1u << (2 * nt);
            if (fmaf(-2.0022f, d[nt * 4 + 1], q1) <= m1a) maskA |= 1u << (2 * nt + 1);
            if (fmaf(-2.0022f, d[nt * 4 + 2], q0) <= m1b) maskB |= 1u << (2 * nt);
            if (fmaf(-2.0022f, d[nt * 4 + 3], q1) <= m1b) maskB |= 1u << (2 * nt + 1);
        }

        // ---- pass 3: exact fp32 refine (4-way split dot; cand rows via L1) ----
        float bva = 3.402823e38f, bvb = 3.402823e38f;
        int bka = NCAND, bkb = NCAND;
        {
            const float2* srowA = (const float2*)(sp + SM_A32 + curof + (uint32_t)ra * A32ROW);
            uint32_t mk = maskA;
            while (mk) {
                int i = __ffs(mk) - 1; mk &= mk - 1;
                int k = ((i >> 1) << 3) + colbase + (i & 1);
                const float2* crow = (const float2*)(g_candT + k * CTPAD);
                float t0 = 0.0f, t1 = 0.0f, t2 = 0.0f, t3 = 0.0f;
#pragma unroll
                for (int j = 0; j < 24; j += 4) {
                    float2 s0 = srowA[j],     c0 = __ldg(crow + j);
                    float2 s1 = srowA[j + 1], c1 = __ldg(crow + j + 1);
                    float2 s2 = srowA[j + 2], c2v = __ldg(crow + j + 2);
                    float2 s3 = srowA[j + 3], c3 = __ldg(crow + j + 3);
                    t0 = fmaf(s0.x, c0.x, fmaf(s0.y, c0.y, t0));
                    t1 = fmaf(s1.x, c1.x, fmaf(s1.y, c1.y, t1));
                    t2 = fmaf(s2.x, c2v.x, fmaf(s2.y, c2v.y, t2));
                    t3 = fmaf(s3.x, c3.x, fmaf(s3.y, c3.y, t3));
                }
                {
                    float2 s0 = srowA[24], c0 = __ldg(crow + 24);
                    float2 s1 = srowA[25], c1 = __ldg(crow + 25);
                    float2 s2 = srowA[26], c2v = __ldg(crow + 26);
                    t0 = fmaf(s0.x, c0.x, fmaf(s0.y, c0.y, t0));
                    t1 = fmaf(s1.x, c1.x, fmaf(s1.y, c1.y, t1));
                    t2 = fmaf(s2.x, c2v.x, fmaf(s2.y, c2v.y, t2));
                }
                float dt = (t0 + t1) + (t2 + t3);
                float ev = fmaf(-2.0f, dt, c2ps[k] - 1e-6f);
                if (ev < bva || (ev == bva && k < bka)) { bva = ev; bka = k; }
            }
            const float2* srowB = (const float2*)(sp + SM_A32 + curof + (uint32_t)(ra + 8) * A32ROW);
            mk = maskB;
            while (mk) {
                int i = __ffs(mk) - 1; mk &= mk - 1;
                int k = ((i >> 1) << 3) + colbase + (i & 1);
                const float2* crow = (const float2*)(g_candT + k * CTPAD);
                float t0 = 0.0f, t1 = 0.0f, t2 = 0.0f, t3 = 0.0f;
#pragma unroll
                for (int j = 0; j < 24; j += 4) {
                    float2 s0 = srowB[j],     c0 = __ldg(crow + j);
                    float2 s1 = srowB[j + 1], c1 = __ldg(crow + j + 1);
                    float2 s2 = srowB[j + 2], c2v = __ldg(crow + j + 2);
                    float2 s3 = srowB[j + 3], c3 = __ldg(crow + j + 3);
                    t0 = fmaf(s0.x, c0.x, fmaf(s0.y, c0.y, t0));
                    t1 = fmaf(s1.x, c1.x, fmaf(s1.y, c1.y, t1));
                    t2 = fmaf(s2.x, c2v.x, fmaf(s2.y, c2v.y, t2));
                    t3 = fmaf(s3.x, c3.x, fmaf(s3.y, c3.y, t3));
                }
                {
                    float2 s0 = srowB[24], c0 = __ldg(crow + 24);
                    float2 s1 = srowB[25], c1 = __ldg(crow + 25);
                    float2 s2 = srowB[26], c2v = __ldg(crow + 26);
                    t0 = fmaf(s0.x, c0.x, fmaf(s0.y, c0.y, t0));
                    t1 = fmaf(s1.x, c1.x, fmaf(s1.y, c1.y, t1));
                    t2 = fmaf(s2.x, c2v.x, fmaf(s2.y, c2v.y, t2));
                }
                float dt = (t0 + t1) + (t2 + t3);
                float ev = fmaf(-2.0f, dt, c2ps[k] - 1e-6f);
                if (ev < bvb || (ev == bvb && k < bkb)) { bvb = ev; bkb = k; }
            }
        }
#pragma unroll
        for (int off = 1; off <= 2; off <<= 1) {
            float ov = __shfl_xor_sync(0xffffffffu, bva, off);
            int   ok = __shfl_xor_sync(0xffffffffu, bka, off);
            if (ov < bva || (ov == bva && ok < bka)) { bva = ov; bka = ok; }
            ov = __shfl_xor_sync(0xffffffffu, bvb, off);
            ok = __shfl_xor_sync(0xffffffffu, bkb, off);
            if (ov < bvb || (ov == bvb && ok < bkb)) { bvb = ov; bkb = ok; }
        }
        if ((lane & 3) == 0) {
            int q = lane >> 2;
            mkw[q] = bka;
            mvw[q] = bva;
            mkw[q + 8] = bkb;
            mvw[q + 8] = bvb;
        }
        __syncwarp();

        // ---- scalar outputs (lanes 0..15, own pixels) ----
        if (lane < 16) {
            long long n = wbase + lane;
            if (n < N) {
                int kmin = mkw[lane];
                int m = kmin / TT;
                out[n] = ((const float*)(sp + SM_TC))[kmin - m * TT];
                out[55 * NN + n] = 0.5f;
                out[56 * NN + n] = 0.0f;
                out[57 * NN + n] = ((const float*)(sp + SM_LM))[m];
                acc += (double)mvw[lane];
            }
        }

        // ---- warp-local coalesced best_e + s_recon (own 16 pixels) ----
        {
            long long rem = N - wbase;
            int npx = rem < 16 ? (rem < 0 ? 0 : (int)rem) : 16;
            int limit = npx * CP;                       // up to 432 float2 elems
            float2* eo = (float2*)(out + NN) + wbase * CP;
            float2* ro = (float2*)(out + 58 * NN) + wbase * CP;
            const float* libs = (const float*)(sp + SM_LIB);
            for (int i = lane; i < limit; i += 32) {
                int p = i / CP;
                int j = i - p * CP;
                int k = mkw[p];
                int m = k / TT;
                float2 e = *(const float2*)(libs + m * CC + 2 * j);
                float2 rv = __ldg((const float2*)(g_candT + k * CTPAD) + j);
                eo[i] = e;
                ro[i] = rv;
            }
        }
        __syncwarp();
        pb ^= 1u;
    }

    // ---- objective reduce ----
    __syncthreads();
    double* red = (double*)(sp + SM_A);
    red[tid] = acc;
    __syncthreads();
#pragma unroll
    for (int s = 128; s > 0; s >>= 1) {
        if (tid < s) red[tid] += red[tid + s];
        __syncthreads();
    }
    if (tid == 0) atomicAdd(&g_obj, red[0]);
}

__global__ void hadar_finalize(float* __restrict__ out, int N) {
    out[112LL * N] = (float)(g_obj / (double)N);
}

// ---------------------------------------------------------------------------
extern "C" void kernel_launch(void* const* d_in, const int* in_sizes, int n_in,
                              void* d_out, int out_size) {
    const float* s_obs    = (const float*)d_in[0];
    const float* s_sky    = (const float*)d_in[1];
    const float* s_ground = (const float*)d_in[2];
    const float* library  = (const float*)d_in[3];
    const float* wg       = (const float*)d_in[4];
    float* out = (float*)d_out;
    int C = in_sizes[1];           // 54
    int N = in_sizes[0] / C;       // 1048576

    cudaFuncSetAttribute(hadar_main_mma, cudaFuncAttributeMaxDynamicSharedMemorySize, DYNSMEM);

    hadar_setup<<<1, 512>>>(s_sky, s_ground, library, wg);
    hadar_main_mma<<<296, 256, DYNSMEM>>>(s_obs, library, out, N);
    hadar_finalize<<<1, 1>>>(out, N);
}